// round 7
// baseline (speedup 1.0000x reference)
#include <cuda_runtime.h>
#include <stdint.h>

// BasedKernel feature map, d=16:
//   out[row, 0]        = 1
//   out[row, 1..16]    = x[row, j-1] * 0.5
//   out[row, 17+idx]   = x[row, idx>>4] * x[row, idx&15] * SC2,  idx = 0..255
//
// R7: persistent blocks + double-buffered smem + pipelined TMA bulk stores.
// R4's 8-row/256-thread tile (the best measured config) but each block now
// processes 16 tiles, flushing tile p's buffer via cp.async.bulk while
// computing tile p+1 into the other buffer (wait_group.read 1 = one
// outstanding flush). Removes the per-CTA blocking TMA tail that capped
// DRAM at 67%.

#define SC2 0.17677669529663687f

#define ROWS_PER_TILE 8
#define THREADS       256
#define FLOATS_PER_TILE (ROWS_PER_TILE * 273)        // 2184
#define BYTES_PER_TILE  (FLOATS_PER_TILE * 4)        // 8736, multiple of 16

__global__ void __launch_bounds__(THREADS, 8)
based_feature_kernel(const float* __restrict__ x,
                     float* __restrict__ out,
                     int n_tiles)
{
    __shared__ __align__(16) float buf[2][FLOATS_PER_TILE];

    const int tid  = threadIdx.x;
    const int warp = tid >> 5;                 // 0..7 = local row
    const int lane = tid & 31;
    const int hi   = lane >> 4;                // 0 or 1

    int p = 0;

    for (int tile = blockIdx.x; tile < n_tiles; tile += gridDim.x) {
        // Ensure the flush issued 2 iterations ago (which read buf[p]) is done.
        if (tid == 0)
            asm volatile("cp.async.bulk.wait_group.read 1;" ::: "memory");
        __syncthreads();

        // ---- compute one row per warp into buf[p] ----
        const int row = tile * ROWS_PER_TILE + warp;
        const float* xr = x + (size_t)row * 16;
        float v = (lane < 16) ? __ldg(xr + lane) : 0.0f;

        float* o = buf[p] + warp * 273;

        // Convergent shfl first (full warp).
        const float b2 = __shfl_sync(0xffffffffu, v, lane & 15) * SC2;

        // Header (shfl-free, predicated stores).
        if (lane < 16) o[1 + lane] = v * 0.5f;
        if (lane == 16) o[0] = 1.0f;

        // Quadratic: idx = 32m + lane, i = 2m + hi, k = lane&15.
#pragma unroll
        for (int m = 0; m < 8; ++m) {
            const float a = __shfl_sync(0xffffffffu, v, 2 * m + hi);
            o[17 + 32 * m + lane] = a * b2;
        }

        __syncthreads();

        // ---- issue async flush of buf[p]; do NOT wait here ----
        if (tid == 0) {
            uint32_t saddr;
            asm volatile(
                "{ .reg .u64 t; cvta.to.shared.u64 t, %1; cvt.u32.u64 %0, t; }"
                : "=r"(saddr) : "l"(buf[p]));

            float* g = out + (size_t)tile * FLOATS_PER_TILE;

            asm volatile("fence.proxy.async.shared::cta;" ::: "memory");
            asm volatile(
                "cp.async.bulk.global.shared::cta.bulk_group [%0], [%1], %2;"
                :: "l"(g), "r"(saddr), "n"(BYTES_PER_TILE) : "memory");
            asm volatile("cp.async.bulk.commit_group;" ::: "memory");
        }

        p ^= 1;
    }

    // Drain all outstanding flushes before the CTA exits (smem lifetime).
    if (tid == 0)
        asm volatile("cp.async.bulk.wait_group.read 0;" ::: "memory");
}

extern "C" void kernel_launch(void* const* d_in, const int* in_sizes, int n_in,
                              void* d_out, int out_size)
{
    const float* x = (const float*)d_in[0];
    float* out = (float*)d_out;

    const int n_rows  = in_sizes[0] / 16;             // 262144
    const int n_tiles = n_rows / ROWS_PER_TILE;       // 32768

    const int blocks = 2048;                          // 16 tiles per block

    based_feature_kernel<<<blocks, THREADS>>>(x, out, n_tiles);
}